// round 1
// baseline (speedup 1.0000x reference)
#include <cuda_runtime.h>
#include <math.h>

// Problem constants (fixed by setup_inputs)
#define BATCH 2
#define SEQ   2048
#define DIM   4096
#define NH    32
#define NKV   8
#define HD    128
#define NREP  4
#define MTOT  (BATCH*SEQ)   // 4096

// -------- scratch (device globals: no allocation allowed) --------
__device__ float g_q[(size_t)BATCH*SEQ*NH*HD];   // 64 MB
__device__ float g_k[(size_t)BATCH*SEQ*NKV*HD];  // 16 MB
__device__ float g_v[(size_t)BATCH*SEQ*NKV*HD];  // 16 MB
__device__ float g_o[(size_t)BATCH*SEQ*NH*HD];   // 64 MB

// ============================================================
// SGEMM: C[M,N] = A[M,K] @ B[K,N], row-major, fp32.
// 128x128 block tile, BK=8, 256 threads, 8x8 per-thread microtile.
// M,N,K must be multiples of 128/128/8 (true for all our shapes).
// ============================================================
__global__ void __launch_bounds__(256) sgemm128(const float* __restrict__ A,
                                                const float* __restrict__ Bm,
                                                float* __restrict__ C,
                                                int M, int N, int K)
{
    const int BK = 8;
    __shared__ float As[BK][128];   // stored transposed: As[k][m]
    __shared__ float Bs[BK][128];

    int t = threadIdx.x;
    int brow = blockIdx.y * 128;
    int bcol = blockIdx.x * 128;
    int ty = t >> 4;        // 0..15  -> row group
    int tx = t & 15;        // 0..15  -> col group

    // loader mapping
    int arow = t >> 1;            // 0..127
    int acol = (t & 1) * 4;       // 0 or 4
    int brow2 = t >> 5;           // 0..7
    int bcol2 = (t & 31) * 4;     // 0..124

    float acc[8][8];
    #pragma unroll
    for (int i = 0; i < 8; i++)
        #pragma unroll
        for (int j = 0; j < 8; j++) acc[i][j] = 0.f;

    const float* Aptr = A + (size_t)(brow + arow) * K + acol;
    const float* Bptr = Bm + (size_t)brow2 * N + bcol + bcol2;

    for (int k0 = 0; k0 < K; k0 += BK) {
        float4 av = *(const float4*)(Aptr + k0);
        As[acol + 0][arow] = av.x;
        As[acol + 1][arow] = av.y;
        As[acol + 2][arow] = av.z;
        As[acol + 3][arow] = av.w;
        float4 bv = *(const float4*)(Bptr + (size_t)k0 * N);
        *(float4*)&Bs[brow2][bcol2] = bv;
        __syncthreads();

        #pragma unroll
        for (int kk = 0; kk < BK; kk++) {
            float ra[8], rb[8];
            #pragma unroll
            for (int i = 0; i < 8; i++) ra[i] = As[kk][ty * 8 + i];
            #pragma unroll
            for (int j = 0; j < 8; j++) rb[j] = Bs[kk][tx * 8 + j];
            #pragma unroll
            for (int i = 0; i < 8; i++)
                #pragma unroll
                for (int j = 0; j < 8; j++)
                    acc[i][j] += ra[i] * rb[j];
        }
        __syncthreads();
    }

    #pragma unroll
    for (int i = 0; i < 8; i++) {
        size_t r = (size_t)(brow + ty * 8 + i);
        #pragma unroll
        for (int j = 0; j < 8; j += 4) {
            float4 v = make_float4(acc[i][j], acc[i][j+1], acc[i][j+2], acc[i][j+3]);
            *(float4*)(C + r * N + bcol + tx * 8 + j) = v;
        }
    }
}

// ============================================================
// RoPE (in-place) on g_q (NH heads) and g_k (NKV heads).
// One thread per (complex) pair.
// ============================================================
__global__ void rope_kernel(float* __restrict__ q, float* __restrict__ k,
                            const float* __restrict__ cos_, const float* __restrict__ sin_)
{
    const int HD2 = HD / 2;
    const int nq = BATCH * SEQ * NH * HD2;
    const int nk = BATCH * SEQ * NKV * HD2;
    int idx = blockIdx.x * blockDim.x + threadIdx.x;
    if (idx < nq) {
        int d2 = idx % HD2;
        int rest = idx / HD2;          // (b*SEQ+s)*NH + h
        int s = (rest / NH) % SEQ;
        float c = cos_[s * HD2 + d2];
        float sn = sin_[s * HD2 + d2];
        float re = q[2 * idx], im = q[2 * idx + 1];
        q[2 * idx]     = re * c - im * sn;
        q[2 * idx + 1] = re * sn + im * c;
    } else if (idx < nq + nk) {
        int j = idx - nq;
        int d2 = j % HD2;
        int rest = j / HD2;            // (b*SEQ+s)*NKV + h
        int s = (rest / NKV) % SEQ;
        float c = cos_[s * HD2 + d2];
        float sn = sin_[s * HD2 + d2];
        float re = k[2 * j], im = k[2 * j + 1];
        k[2 * j]     = re * c - im * sn;
        k[2 * j + 1] = re * sn + im * c;
    }
}

// ============================================================
// Flash-style attention (fp32, non-causal, online softmax).
// Grid: (SEQ/64, NH, BATCH). Block: 256 threads (8 warps).
// Warp w owns 8 query rows; lane l owns keys {l, l+32} in the score
// phase and output cols {l, l+32, l+64, l+96} in the PV phase.
// SMEM: Qs[64][128] + Ks[64][129](pad) + Vs[64][128] + Ps[64][64]
// ============================================================
#define BQ 64
#define BKT 64
#define KPAD 129

__global__ void __launch_bounds__(256) attn_kernel(const float* __restrict__ Q,
                                                   const float* __restrict__ Kg,
                                                   const float* __restrict__ Vg,
                                                   float* __restrict__ O)
{
    extern __shared__ float smf[];
    float* Qs = smf;                     // 64*128
    float* Ks = Qs + BQ * HD;            // 64*129
    float* Vs = Ks + BKT * KPAD;         // 64*128
    float* Ps = Vs + BKT * HD;           // 64*64

    int qt = blockIdx.x;
    int h  = blockIdx.y;
    int b  = blockIdx.z;
    int kvh = h / NREP;
    int t = threadIdx.x;
    int w = t >> 5, l = t & 31;

    const float qscale = 0.08838834764831845f;  // 1/sqrt(HD)

    // load and pre-scale Q tile
    for (int i = t; i < BQ * HD; i += 256) {
        int r = i / HD, d = i % HD;
        size_t gidx = ((size_t)(b * SEQ + qt * BQ + r) * NH + h) * HD + d;
        Qs[r * HD + d] = Q[gidx] * qscale;
    }

    float m[8], lsum[8], o[8][4];
    #pragma unroll
    for (int i = 0; i < 8; i++) {
        m[i] = -1e30f; lsum[i] = 0.f;
        #pragma unroll
        for (int j = 0; j < 4; j++) o[i][j] = 0.f;
    }

    for (int kt = 0; kt < SEQ / BKT; kt++) {
        __syncthreads();   // Qs ready (first iter) / previous PV done
        for (int i = t; i < BKT * HD; i += 256) {
            int r = i / HD, d = i % HD;
            size_t gidx = ((size_t)(b * SEQ + kt * BKT + r) * NKV + kvh) * HD + d;
            Ks[r * KPAD + d] = Kg[gidx];
            Vs[r * HD + d]   = Vg[gidx];
        }
        __syncthreads();

        // ---- scores: rows w*8..w*8+7, keys l and l+32 ----
        float sc0[8], sc1[8];
        #pragma unroll
        for (int i = 0; i < 8; i++) { sc0[i] = 0.f; sc1[i] = 0.f; }
        for (int d = 0; d < HD; d++) {
            float k0 = Ks[l * KPAD + d];
            float k1 = Ks[(l + 32) * KPAD + d];
            #pragma unroll
            for (int i = 0; i < 8; i++) {
                float qv = Qs[(w * 8 + i) * HD + d];
                sc0[i] += qv * k0;
                sc1[i] += qv * k1;
            }
        }

        // ---- online softmax per row ----
        #pragma unroll
        for (int i = 0; i < 8; i++) {
            float mx = fmaxf(sc0[i], sc1[i]);
            #pragma unroll
            for (int off = 16; off > 0; off >>= 1)
                mx = fmaxf(mx, __shfl_xor_sync(0xffffffffu, mx, off));
            float mnew = fmaxf(m[i], mx);
            float alpha = __expf(m[i] - mnew);
            float p0 = __expf(sc0[i] - mnew);
            float p1 = __expf(sc1[i] - mnew);
            float ssum = p0 + p1;
            #pragma unroll
            for (int off = 16; off > 0; off >>= 1)
                ssum += __shfl_xor_sync(0xffffffffu, ssum, off);
            lsum[i] = lsum[i] * alpha + ssum;
            m[i] = mnew;
            #pragma unroll
            for (int j = 0; j < 4; j++) o[i][j] *= alpha;
            Ps[(w * 8 + i) * BKT + l]      = p0;
            Ps[(w * 8 + i) * BKT + l + 32] = p1;
        }
        __syncwarp();   // Ps is warp-private (own 8 rows only)

        // ---- O += P @ V ----
        for (int k = 0; k < BKT; k++) {
            float v0 = Vs[k * HD + l];
            float v1 = Vs[k * HD + l + 32];
            float v2 = Vs[k * HD + l + 64];
            float v3 = Vs[k * HD + l + 96];
            #pragma unroll
            for (int i = 0; i < 8; i++) {
                float p = Ps[(w * 8 + i) * BKT + k];
                o[i][0] += p * v0;
                o[i][1] += p * v1;
                o[i][2] += p * v2;
                o[i][3] += p * v3;
            }
        }
    }

    // ---- epilogue: normalize and write [B,S,NH*HD] ----
    #pragma unroll
    for (int i = 0; i < 8; i++) {
        float inv = 1.f / lsum[i];
        int r = qt * BQ + w * 8 + i;
        size_t base = ((size_t)(b * SEQ + r) * NH + h) * HD;
        O[base + l]      = o[i][0] * inv;
        O[base + l + 32] = o[i][1] * inv;
        O[base + l + 64] = o[i][2] * inv;
        O[base + l + 96] = o[i][3] * inv;
    }
}

// ============================================================
// launch
// ============================================================
extern "C" void kernel_launch(void* const* d_in, const int* in_sizes, int n_in,
                              void* d_out, int out_size)
{
    const float* x  = (const float*)d_in[0];
    const float* wq = (const float*)d_in[1];
    const float* wk = (const float*)d_in[2];
    const float* wv = (const float*)d_in[3];
    const float* wo = (const float*)d_in[4];
    // d_in[5], d_in[6] = zero caches (start_pos=0 -> no effect on output)
    const float* fcos = (const float*)d_in[7];
    const float* fsin = (const float*)d_in[8];
    float* out = (float*)d_out;

    float *gq, *gk, *gv, *go;
    cudaGetSymbolAddress((void**)&gq, g_q);
    cudaGetSymbolAddress((void**)&gk, g_k);
    cudaGetSymbolAddress((void**)&gv, g_v);
    cudaGetSymbolAddress((void**)&go, g_o);

    // 1) projections
    {
        dim3 blk(256);
        dim3 gq_grid(NH * HD / 128, MTOT / 128);    // (32, 32)
        dim3 gkv_grid(NKV * HD / 128, MTOT / 128);  // (8, 32)
        sgemm128<<<gq_grid, blk>>>(x, wq, gq, MTOT, NH * HD, DIM);
        sgemm128<<<gkv_grid, blk>>>(x, wk, gk, MTOT, NKV * HD, DIM);
        sgemm128<<<gkv_grid, blk>>>(x, wv, gv, MTOT, NKV * HD, DIM);
    }

    // 2) RoPE on Q and K
    {
        int total = BATCH * SEQ * (NH + NKV) * (HD / 2);
        rope_kernel<<<(total + 255) / 256, 256>>>(gq, gk, fcos, fsin);
    }

    // 3) attention
    {
        size_t smem = (size_t)(BQ * HD + BKT * KPAD + BKT * HD + BQ * BKT) * sizeof(float);
        cudaFuncSetAttribute(attn_kernel, cudaFuncAttributeMaxDynamicSharedMemorySize, (int)smem);
        dim3 grid(SEQ / BQ, NH, BATCH);
        attn_kernel<<<grid, 256, smem>>>(gq, gk, gv, go);
    }

    // 4) output projection
    {
        dim3 blk(256);
        dim3 grid(DIM / 128, MTOT / 128);           // (32, 32)
        sgemm128<<<grid, blk>>>(go, wo, out, MTOT, DIM, DIM);
    }
}

// round 3
// speedup vs baseline: 2.0287x; 2.0287x over previous
#include <cuda_runtime.h>
#include <cuda_bf16.h>
#include <cstdint>
#include <math.h>

// Problem constants (fixed by setup_inputs)
#define BATCH 2
#define SEQ   2048
#define DIM   4096
#define NH    32
#define NKV   8
#define HD    128
#define NREP  4
#define MTOT  (BATCH*SEQ)   // 4096
#define NQ    (NH*HD)       // 4096
#define NKVD  (NKV*HD)      // 1024

// -------- scratch (device globals: no allocation allowed) --------
__device__ float g_q[(size_t)MTOT*NQ];     // 64 MB
__device__ float g_k[(size_t)MTOT*NKVD];   // 16 MB
__device__ float g_v[(size_t)MTOT*NKVD];   // 16 MB
__device__ float g_o[(size_t)MTOT*NQ];     // 64 MB

__device__ __nv_bfloat16 g_xh[(size_t)MTOT*DIM],  g_xl[(size_t)MTOT*DIM];
__device__ __nv_bfloat16 g_wqTh[(size_t)NQ*DIM],  g_wqTl[(size_t)NQ*DIM];
__device__ __nv_bfloat16 g_wkTh[(size_t)NKVD*DIM],g_wkTl[(size_t)NKVD*DIM];
__device__ __nv_bfloat16 g_wvTh[(size_t)NKVD*DIM],g_wvTl[(size_t)NKVD*DIM];
__device__ __nv_bfloat16 g_woTh[(size_t)DIM*NQ],  g_woTl[(size_t)DIM*NQ];
__device__ __nv_bfloat16 g_aoh[(size_t)MTOT*NQ],  g_aol[(size_t)MTOT*NQ];

// ============================================================
// PTX helpers (baseline PTX only — valid on compute_103)
// ============================================================
__device__ __forceinline__ uint32_t smem_u32(const void* p) {
    uint32_t a;
    asm("{ .reg .u64 t; cvta.to.shared.u64 t, %1; cvt.u32.u64 %0, t; }" : "=r"(a) : "l"(p));
    return a;
}
__device__ __forceinline__ void cp16(uint32_t dst, const void* src) {
    asm volatile("cp.async.cg.shared.global [%0], [%1], 16;" :: "r"(dst), "l"(src));
}
#define CP_COMMIT()  asm volatile("cp.async.commit_group;")
#define CP_WAIT1()   asm volatile("cp.async.wait_group 1;")
#define CP_WAIT0()   asm volatile("cp.async.wait_group 0;")

__device__ __forceinline__ void ldsm4(uint32_t* r, uint32_t addr) {
    asm volatile("ldmatrix.sync.aligned.m8n8.x4.shared.b16 {%0,%1,%2,%3}, [%4];"
        : "=r"(r[0]), "=r"(r[1]), "=r"(r[2]), "=r"(r[3]) : "r"(addr));
}
__device__ __forceinline__ void ldsm2(uint32_t* r, uint32_t addr) {
    asm volatile("ldmatrix.sync.aligned.m8n8.x2.shared.b16 {%0,%1}, [%2];"
        : "=r"(r[0]), "=r"(r[1]) : "r"(addr));
}
__device__ __forceinline__ void mma16816(float* c, const uint32_t* a, const uint32_t* b) {
    asm volatile("mma.sync.aligned.m16n8k16.row.col.f32.bf16.bf16.f32 "
        "{%0,%1,%2,%3}, {%4,%5,%6,%7}, {%8,%9}, {%0,%1,%2,%3};"
        : "+f"(c[0]), "+f"(c[1]), "+f"(c[2]), "+f"(c[3])
        : "r"(a[0]), "r"(a[1]), "r"(a[2]), "r"(a[3]), "r"(b[0]), "r"(b[1]));
}

// ============================================================
// mma.sync split-bf16 GEMM: C[M,N] = (Ah+Al)[M,K] @ (Bh+Bl)[N,K]^T
// (B pre-transposed [N,K] K-major). CTA 128x128, BK=32, 8 warps (2x4),
// warp tile 64x32, double-buffered cp.async, XOR-swizzled SMEM.
// ============================================================
#define BM 128
#define BN 128
#define BK 32
#define OFF_AH 0u
#define OFF_AL 8192u
#define OFF_BH 16384u
#define OFF_BL 24576u
#define STAGE  32768u
#define GEMM_SMEM (2*32768)

// swizzled byte offset inside one 128x32-bf16 tile (row-major, 64B rows)
__device__ __forceinline__ uint32_t swz(int row, int seg) {
    return (uint32_t)row * 64u + ((uint32_t)(seg ^ ((row >> 1) & 3)) << 4);
}

__global__ void __launch_bounds__(256) gemm_mma(
    const __nv_bfloat16* __restrict__ Ah, const __nv_bfloat16* __restrict__ Al,
    const __nv_bfloat16* __restrict__ Bh, const __nv_bfloat16* __restrict__ Bl,
    float* __restrict__ C, int M, int N, int K)
{
    extern __shared__ char smem[];
    const uint32_t sb = smem_u32(smem);
    const int t = threadIdx.x;
    const int lane = t & 31, wid = t >> 5;
    const int m0 = blockIdx.y * BM, n0 = blockIdx.x * BN;

    // ---- loader mapping: thread t covers row lr, segments ls, ls+1 (16B each) ----
    const int lr = t >> 1;
    const int ls = (t & 1) * 2;
    const __nv_bfloat16* gAh = Ah + (size_t)(m0 + lr) * K + ls * 8;
    const __nv_bfloat16* gAl = Al + (size_t)(m0 + lr) * K + ls * 8;
    const __nv_bfloat16* gBh = Bh + (size_t)(n0 + lr) * K + ls * 8;
    const __nv_bfloat16* gBl = Bl + (size_t)(n0 + lr) * K + ls * 8;
    const uint32_t d0 = swz(lr, ls), d1 = swz(lr, ls + 1);

#define LOAD_CHUNK(k0, base) do {                         \
    cp16((base) + OFF_AH + d0, gAh + (k0));               \
    cp16((base) + OFF_AH + d1, gAh + (k0) + 8);           \
    cp16((base) + OFF_AL + d0, gAl + (k0));               \
    cp16((base) + OFF_AL + d1, gAl + (k0) + 8);           \
    cp16((base) + OFF_BH + d0, gBh + (k0));               \
    cp16((base) + OFF_BH + d1, gBh + (k0) + 8);           \
    cp16((base) + OFF_BL + d0, gBl + (k0));               \
    cp16((base) + OFF_BL + d1, gBl + (k0) + 8);           \
} while (0)

    // ---- compute mapping ----
    const int wm = (wid >> 2) * 64;     // warp M offset in tile
    const int wn = (wid & 3) * 32;      // warp N offset in tile
    const int a_row_base = wm + (lane & 7) + ((lane >> 3) & 1) * 8;
    const int a_seg_base = (lane >> 4);
    const int l2 = lane & 15;
    const int b_row_base = wn + (l2 & 7);
    const int b_seg_base = (l2 >> 3);

    float acc[4][4][4];
    #pragma unroll
    for (int i = 0; i < 4; i++)
        #pragma unroll
        for (int j = 0; j < 4; j++)
            #pragma unroll
            for (int v = 0; v < 4; v++) acc[i][j][v] = 0.f;

    const int nch = K / BK;
    LOAD_CHUNK(0, sb);          CP_COMMIT();
    LOAD_CHUNK(BK, sb + STAGE); CP_COMMIT();

    for (int ch = 0; ch < nch; ch++) {
        CP_WAIT1();
        __syncthreads();
        const uint32_t base = sb + (uint32_t)(ch & 1) * STAGE;

        #pragma unroll
        for (int ks = 0; ks < 2; ks++) {
            uint32_t ah[4][4], al[4][4], bh[4][2], bl[4][2];
            #pragma unroll
            for (int mt = 0; mt < 4; mt++) {
                int row = a_row_base + mt * 16;
                int seg = a_seg_base + ks * 2;
                uint32_t off = swz(row, seg);
                ldsm4(ah[mt], base + OFF_AH + off);
                ldsm4(al[mt], base + OFF_AL + off);
            }
            #pragma unroll
            for (int nt = 0; nt < 4; nt++) {
                int row = b_row_base + nt * 8;
                int seg = b_seg_base + ks * 2;
                uint32_t off = swz(row, seg);
                ldsm2(bh[nt], base + OFF_BH + off);
                ldsm2(bl[nt], base + OFF_BL + off);
            }
            #pragma unroll
            for (int mt = 0; mt < 4; mt++)
                #pragma unroll
                for (int nt = 0; nt < 4; nt++) {
                    mma16816(acc[mt][nt], ah[mt], bh[nt]);
                    mma16816(acc[mt][nt], ah[mt], bl[nt]);
                    mma16816(acc[mt][nt], al[mt], bh[nt]);
                }
        }
        __syncthreads();
        if (ch + 2 < nch) LOAD_CHUNK((ch + 2) * BK, base);
        CP_COMMIT();
    }

    // ---- epilogue ----
    #pragma unroll
    for (int mt = 0; mt < 4; mt++) {
        int r0 = m0 + wm + mt * 16 + (lane >> 2);
        #pragma unroll
        for (int nt = 0; nt < 4; nt++) {
            int c0 = n0 + wn + nt * 8 + (lane & 3) * 2;
            float2 v0 = make_float2(acc[mt][nt][0], acc[mt][nt][1]);
            float2 v1 = make_float2(acc[mt][nt][2], acc[mt][nt][3]);
            *(float2*)(C + (size_t)r0 * N + c0)       = v0;
            *(float2*)(C + (size_t)(r0 + 8) * N + c0) = v1;
        }
    }
#undef LOAD_CHUNK
}

// ============================================================
// fp32 -> bf16 hi/lo split (element-wise), float2 vectorized
// ============================================================
__global__ void split2(const float* __restrict__ src, __nv_bfloat16* __restrict__ hi,
                       __nv_bfloat16* __restrict__ lo, int n2)
{
    int i = blockIdx.x * blockDim.x + threadIdx.x;
    if (i < n2) {
        float2 v = ((const float2*)src)[i];
        __nv_bfloat16 hx = __float2bfloat16(v.x), hy = __float2bfloat16(v.y);
        float rx = v.x - __bfloat162float(hx);
        float ry = v.y - __bfloat162float(hy);
        ((__nv_bfloat162*)hi)[i] = __halves2bfloat162(hx, hy);
        ((__nv_bfloat162*)lo)[i] = __halves2bfloat162(__float2bfloat16(rx), __float2bfloat16(ry));
    }
}

// ============================================================
// W[K,N] fp32 -> WT hi/lo bf16 [N,K]  (tiled transpose + split)
// ============================================================
__global__ void transpose_split(const float* __restrict__ W, __nv_bfloat16* __restrict__ Th,
                                __nv_bfloat16* __restrict__ Tl, int K, int N)
{
    __shared__ float tile[32][33];
    int tx = threadIdx.x, ty = threadIdx.y;
    int n = blockIdx.x * 32 + tx;
    #pragma unroll
    for (int j = 0; j < 4; j++) {
        int k = blockIdx.y * 32 + ty + j * 8;
        tile[ty + j * 8][tx] = W[(size_t)k * N + n];
    }
    __syncthreads();
    int k2 = blockIdx.y * 32 + tx;
    #pragma unroll
    for (int j = 0; j < 4; j++) {
        int n2 = blockIdx.x * 32 + ty + j * 8;
        float v = tile[tx][ty + j * 8];
        __nv_bfloat16 h = __float2bfloat16(v);
        Th[(size_t)n2 * K + k2] = h;
        Tl[(size_t)n2 * K + k2] = __float2bfloat16(v - __bfloat162float(h));
    }
}

// ============================================================
// RoPE (in-place) on g_q (NH heads) and g_k (NKV heads).
// ============================================================
__global__ void rope_kernel(float* __restrict__ q, float* __restrict__ k,
                            const float* __restrict__ cos_, const float* __restrict__ sin_)
{
    const int HD2 = HD / 2;
    const int nq = BATCH * SEQ * NH * HD2;
    const int nk = BATCH * SEQ * NKV * HD2;
    int idx = blockIdx.x * blockDim.x + threadIdx.x;
    if (idx < nq) {
        int d2 = idx % HD2;
        int rest = idx / HD2;
        int s = (rest / NH) % SEQ;
        float c = cos_[s * HD2 + d2];
        float sn = sin_[s * HD2 + d2];
        float re = q[2 * idx], im = q[2 * idx + 1];
        q[2 * idx]     = re * c - im * sn;
        q[2 * idx + 1] = re * sn + im * c;
    } else if (idx < nq + nk) {
        int j = idx - nq;
        int d2 = j % HD2;
        int rest = j / HD2;
        int s = (rest / NKV) % SEQ;
        float c = cos_[s * HD2 + d2];
        float sn = sin_[s * HD2 + d2];
        float re = k[2 * j], im = k[2 * j + 1];
        k[2 * j]     = re * c - im * sn;
        k[2 * j + 1] = re * sn + im * c;
    }
}

// ============================================================
// Flash-style attention (fp32, non-causal, online softmax).
// ============================================================
#define BQ 64
#define BKT 64
#define KPAD 129

__global__ void __launch_bounds__(256) attn_kernel(const float* __restrict__ Q,
                                                   const float* __restrict__ Kg,
                                                   const float* __restrict__ Vg,
                                                   float* __restrict__ O)
{
    extern __shared__ float smf[];
    float* Qs = smf;
    float* Ks = Qs + BQ * HD;
    float* Vs = Ks + BKT * KPAD;
    float* Ps = Vs + BKT * HD;

    int qt = blockIdx.x;
    int h  = blockIdx.y;
    int b  = blockIdx.z;
    int kvh = h / NREP;
    int t = threadIdx.x;
    int w = t >> 5, l = t & 31;

    const float qscale = 0.08838834764831845f;

    for (int i = t; i < BQ * HD; i += 256) {
        int r = i / HD, d = i % HD;
        size_t gidx = ((size_t)(b * SEQ + qt * BQ + r) * NH + h) * HD + d;
        Qs[r * HD + d] = Q[gidx] * qscale;
    }

    float m[8], lsum[8], o[8][4];
    #pragma unroll
    for (int i = 0; i < 8; i++) {
        m[i] = -1e30f; lsum[i] = 0.f;
        #pragma unroll
        for (int j = 0; j < 4; j++) o[i][j] = 0.f;
    }

    for (int kt = 0; kt < SEQ / BKT; kt++) {
        __syncthreads();
        for (int i = t; i < BKT * HD; i += 256) {
            int r = i / HD, d = i % HD;
            size_t gidx = ((size_t)(b * SEQ + kt * BKT + r) * NKV + kvh) * HD + d;
            Ks[r * KPAD + d] = Kg[gidx];
            Vs[r * HD + d]   = Vg[gidx];
        }
        __syncthreads();

        float sc0[8], sc1[8];
        #pragma unroll
        for (int i = 0; i < 8; i++) { sc0[i] = 0.f; sc1[i] = 0.f; }
        for (int d = 0; d < HD; d++) {
            float k0 = Ks[l * KPAD + d];
            float k1 = Ks[(l + 32) * KPAD + d];
            #pragma unroll
            for (int i = 0; i < 8; i++) {
                float qv = Qs[(w * 8 + i) * HD + d];
                sc0[i] += qv * k0;
                sc1[i] += qv * k1;
            }
        }

        #pragma unroll
        for (int i = 0; i < 8; i++) {
            float mx = fmaxf(sc0[i], sc1[i]);
            #pragma unroll
            for (int off = 16; off > 0; off >>= 1)
                mx = fmaxf(mx, __shfl_xor_sync(0xffffffffu, mx, off));
            float mnew = fmaxf(m[i], mx);
            float alpha = __expf(m[i] - mnew);
            float p0 = __expf(sc0[i] - mnew);
            float p1 = __expf(sc1[i] - mnew);
            float ssum = p0 + p1;
            #pragma unroll
            for (int off = 16; off > 0; off >>= 1)
                ssum += __shfl_xor_sync(0xffffffffu, ssum, off);
            lsum[i] = lsum[i] * alpha + ssum;
            m[i] = mnew;
            #pragma unroll
            for (int j = 0; j < 4; j++) o[i][j] *= alpha;
            Ps[(w * 8 + i) * BKT + l]      = p0;
            Ps[(w * 8 + i) * BKT + l + 32] = p1;
        }
        __syncwarp();

        for (int k = 0; k < BKT; k++) {
            float v0 = Vs[k * HD + l];
            float v1 = Vs[k * HD + l + 32];
            float v2 = Vs[k * HD + l + 64];
            float v3 = Vs[k * HD + l + 96];
            #pragma unroll
            for (int i = 0; i < 8; i++) {
                float p = Ps[(w * 8 + i) * BKT + k];
                o[i][0] += p * v0;
                o[i][1] += p * v1;
                o[i][2] += p * v2;
                o[i][3] += p * v3;
            }
        }
    }

    #pragma unroll
    for (int i = 0; i < 8; i++) {
        float inv = 1.f / lsum[i];
        int r = qt * BQ + w * 8 + i;
        size_t base = ((size_t)(b * SEQ + r) * NH + h) * HD;
        O[base + l]      = o[i][0] * inv;
        O[base + l + 32] = o[i][1] * inv;
        O[base + l + 64] = o[i][2] * inv;
        O[base + l + 96] = o[i][3] * inv;
    }
}

// ============================================================
// launch
// ============================================================
extern "C" void kernel_launch(void* const* d_in, const int* in_sizes, int n_in,
                              void* d_out, int out_size)
{
    const float* x  = (const float*)d_in[0];
    const float* wq = (const float*)d_in[1];
    const float* wk = (const float*)d_in[2];
    const float* wv = (const float*)d_in[3];
    const float* wo = (const float*)d_in[4];
    const float* fcos = (const float*)d_in[7];
    const float* fsin = (const float*)d_in[8];
    float* out = (float*)d_out;

    float *gq, *gk, *gv, *go;
    __nv_bfloat16 *xh, *xl, *wqTh, *wqTl, *wkTh, *wkTl, *wvTh, *wvTl, *woTh, *woTl, *aoh, *aol;
    cudaGetSymbolAddress((void**)&gq, g_q);
    cudaGetSymbolAddress((void**)&gk, g_k);
    cudaGetSymbolAddress((void**)&gv, g_v);
    cudaGetSymbolAddress((void**)&go, g_o);
    cudaGetSymbolAddress((void**)&xh, g_xh);   cudaGetSymbolAddress((void**)&xl, g_xl);
    cudaGetSymbolAddress((void**)&wqTh, g_wqTh); cudaGetSymbolAddress((void**)&wqTl, g_wqTl);
    cudaGetSymbolAddress((void**)&wkTh, g_wkTh); cudaGetSymbolAddress((void**)&wkTl, g_wkTl);
    cudaGetSymbolAddress((void**)&wvTh, g_wvTh); cudaGetSymbolAddress((void**)&wvTl, g_wvTl);
    cudaGetSymbolAddress((void**)&woTh, g_woTh); cudaGetSymbolAddress((void**)&woTl, g_woTl);
    cudaGetSymbolAddress((void**)&aoh, g_aoh);  cudaGetSymbolAddress((void**)&aol, g_aol);

    // 0) conversions: x split, weights transpose+split
    {
        int n2 = (int)((size_t)MTOT * DIM / 2);
        split2<<<(n2 + 255) / 256, 256>>>(x, xh, xl, n2);
        transpose_split<<<dim3(NQ / 32, DIM / 32),   dim3(32, 8)>>>(wq, wqTh, wqTl, DIM, NQ);
        transpose_split<<<dim3(NKVD / 32, DIM / 32), dim3(32, 8)>>>(wk, wkTh, wkTl, DIM, NKVD);
        transpose_split<<<dim3(NKVD / 32, DIM / 32), dim3(32, 8)>>>(wv, wvTh, wvTl, DIM, NKVD);
        transpose_split<<<dim3(DIM / 32, NQ / 32),   dim3(32, 8)>>>(wo, woTh, woTl, NQ, DIM);
    }

    // 1) projections (mma.sync split-bf16)
    cudaFuncSetAttribute(gemm_mma, cudaFuncAttributeMaxDynamicSharedMemorySize, GEMM_SMEM);
    gemm_mma<<<dim3(NQ / BN,   MTOT / BM), 256, GEMM_SMEM>>>(xh, xl, wqTh, wqTl, gq, MTOT, NQ,   DIM);
    gemm_mma<<<dim3(NKVD / BN, MTOT / BM), 256, GEMM_SMEM>>>(xh, xl, wkTh, wkTl, gk, MTOT, NKVD, DIM);
    gemm_mma<<<dim3(NKVD / BN, MTOT / BM), 256, GEMM_SMEM>>>(xh, xl, wvTh, wvTl, gv, MTOT, NKVD, DIM);

    // 2) RoPE
    {
        int total = BATCH * SEQ * (NH + NKV) * (HD / 2);
        rope_kernel<<<(total + 255) / 256, 256>>>(gq, gk, fcos, fsin);
    }

    // 3) attention
    {
        size_t smem = (size_t)(BQ * HD + BKT * KPAD + BKT * HD + BQ * BKT) * sizeof(float);
        cudaFuncSetAttribute(attn_kernel, cudaFuncAttributeMaxDynamicSharedMemorySize, (int)smem);
        dim3 grid(SEQ / BQ, NH, BATCH);
        attn_kernel<<<grid, 256, smem>>>(gq, gk, gv, go);
    }

    // 4) output projection
    {
        int n2 = (int)((size_t)MTOT * NQ / 2);
        split2<<<(n2 + 255) / 256, 256>>>(go, aoh, aol, n2);
        gemm_mma<<<dim3(DIM / BN, MTOT / BM), 256, GEMM_SMEM>>>(aoh, aol, woTh, woTl, out, MTOT, DIM, NQ);
    }
}

// round 4
// speedup vs baseline: 3.1064x; 1.5312x over previous
#include <cuda_runtime.h>
#include <cuda_bf16.h>
#include <cstdint>
#include <math.h>

#define BATCH 2
#define SEQ   2048
#define DIM   4096
#define NH    32
#define NKV   8
#define HD    128
#define NREP  4
#define MTOT  (BATCH*SEQ)   // 4096
#define NQ    (NH*HD)       // 4096
#define NKVD  (NKV*HD)      // 1024

// -------- scratch (device globals) --------
__device__ float g_q[(size_t)MTOT*NQ];     // fp32 projection outputs
__device__ float g_k[(size_t)MTOT*NKVD];
__device__ float g_v[(size_t)MTOT*NKVD];

__device__ __nv_bfloat16 g_xh[(size_t)MTOT*DIM],  g_xl[(size_t)MTOT*DIM];
__device__ __nv_bfloat16 g_wqTh[(size_t)NQ*DIM],  g_wqTl[(size_t)NQ*DIM];
__device__ __nv_bfloat16 g_wkTh[(size_t)NKVD*DIM],g_wkTl[(size_t)NKVD*DIM];
__device__ __nv_bfloat16 g_wvTh[(size_t)NKVD*DIM],g_wvTl[(size_t)NKVD*DIM];
__device__ __nv_bfloat16 g_woTh[(size_t)DIM*NQ],  g_woTl[(size_t)DIM*NQ];
__device__ __nv_bfloat16 g_aoh[(size_t)MTOT*NQ],  g_aol[(size_t)MTOT*NQ];
// rope-split outputs: q [b][h][s][d], k/v [b][kvh][s][d]
__device__ __nv_bfloat16 g_qh[(size_t)MTOT*NQ],   g_ql[(size_t)MTOT*NQ];
__device__ __nv_bfloat16 g_kh[(size_t)MTOT*NKVD], g_kl[(size_t)MTOT*NKVD];
__device__ __nv_bfloat16 g_vh[(size_t)MTOT*NKVD], g_vl[(size_t)MTOT*NKVD];

// ============================================================
// PTX helpers (baseline PTX only)
// ============================================================
__device__ __forceinline__ uint32_t smem_u32(const void* p) {
    uint32_t a;
    asm("{ .reg .u64 t; cvta.to.shared.u64 t, %1; cvt.u32.u64 %0, t; }" : "=r"(a) : "l"(p));
    return a;
}
__device__ __forceinline__ void cp16(uint32_t dst, const void* src) {
    asm volatile("cp.async.cg.shared.global [%0], [%1], 16;" :: "r"(dst), "l"(src));
}
#define CP_COMMIT()  asm volatile("cp.async.commit_group;")
#define CP_WAIT1()   asm volatile("cp.async.wait_group 1;")

__device__ __forceinline__ void ldsm4(uint32_t* r, uint32_t addr) {
    asm volatile("ldmatrix.sync.aligned.m8n8.x4.shared.b16 {%0,%1,%2,%3}, [%4];"
        : "=r"(r[0]), "=r"(r[1]), "=r"(r[2]), "=r"(r[3]) : "r"(addr));
}
__device__ __forceinline__ void ldsm4t(uint32_t* r, uint32_t addr) {
    asm volatile("ldmatrix.sync.aligned.m8n8.x4.trans.shared.b16 {%0,%1,%2,%3}, [%4];"
        : "=r"(r[0]), "=r"(r[1]), "=r"(r[2]), "=r"(r[3]) : "r"(addr));
}
__device__ __forceinline__ void ldsm2(uint32_t* r, uint32_t addr) {
    asm volatile("ldmatrix.sync.aligned.m8n8.x2.shared.b16 {%0,%1}, [%2];"
        : "=r"(r[0]), "=r"(r[1]) : "r"(addr));
}
__device__ __forceinline__ void mma16816(float* c, const uint32_t* a, const uint32_t* b) {
    asm volatile("mma.sync.aligned.m16n8k16.row.col.f32.bf16.bf16.f32 "
        "{%0,%1,%2,%3}, {%4,%5,%6,%7}, {%8,%9}, {%0,%1,%2,%3};"
        : "+f"(c[0]), "+f"(c[1]), "+f"(c[2]), "+f"(c[3])
        : "r"(a[0]), "r"(a[1]), "r"(a[2]), "r"(a[3]), "r"(b[0]), "r"(b[1]));
}
__device__ __forceinline__ uint32_t packbf(float a, float b) {
    __nv_bfloat162 v = __floats2bfloat162_rn(a, b);
    return *(uint32_t*)&v;
}

// ============================================================
// mma.sync split-bf16 GEMM (unchanged from R3, passing)
// ============================================================
#define BM 128
#define BN 128
#define BK 32
#define OFF_AH 0u
#define OFF_AL 8192u
#define OFF_BH 16384u
#define OFF_BL 24576u
#define STAGE  32768u
#define GEMM_SMEM (2*32768)

__device__ __forceinline__ uint32_t swz(int row, int seg) {
    return (uint32_t)row * 64u + ((uint32_t)(seg ^ ((row >> 1) & 3)) << 4);
}

__global__ void __launch_bounds__(256) gemm_mma(
    const __nv_bfloat16* __restrict__ Ah, const __nv_bfloat16* __restrict__ Al,
    const __nv_bfloat16* __restrict__ Bh, const __nv_bfloat16* __restrict__ Bl,
    float* __restrict__ C, int M, int N, int K)
{
    extern __shared__ char smem[];
    const uint32_t sb = smem_u32(smem);
    const int t = threadIdx.x;
    const int lane = t & 31, wid = t >> 5;
    const int m0 = blockIdx.y * BM, n0 = blockIdx.x * BN;

    const int lr = t >> 1;
    const int ls = (t & 1) * 2;
    const __nv_bfloat16* gAh = Ah + (size_t)(m0 + lr) * K + ls * 8;
    const __nv_bfloat16* gAl = Al + (size_t)(m0 + lr) * K + ls * 8;
    const __nv_bfloat16* gBh = Bh + (size_t)(n0 + lr) * K + ls * 8;
    const __nv_bfloat16* gBl = Bl + (size_t)(n0 + lr) * K + ls * 8;
    const uint32_t d0 = swz(lr, ls), d1 = swz(lr, ls + 1);

#define LOAD_CHUNK(k0, base) do {                         \
    cp16((base) + OFF_AH + d0, gAh + (k0));               \
    cp16((base) + OFF_AH + d1, gAh + (k0) + 8);           \
    cp16((base) + OFF_AL + d0, gAl + (k0));               \
    cp16((base) + OFF_AL + d1, gAl + (k0) + 8);           \
    cp16((base) + OFF_BH + d0, gBh + (k0));               \
    cp16((base) + OFF_BH + d1, gBh + (k0) + 8);           \
    cp16((base) + OFF_BL + d0, gBl + (k0));               \
    cp16((base) + OFF_BL + d1, gBl + (k0) + 8);           \
} while (0)

    const int wm = (wid >> 2) * 64;
    const int wn = (wid & 3) * 32;
    const int a_row_base = wm + (lane & 7) + ((lane >> 3) & 1) * 8;
    const int a_seg_base = (lane >> 4);
    const int l2 = lane & 15;
    const int b_row_base = wn + (l2 & 7);
    const int b_seg_base = (l2 >> 3);

    float acc[4][4][4];
    #pragma unroll
    for (int i = 0; i < 4; i++)
        #pragma unroll
        for (int j = 0; j < 4; j++)
            #pragma unroll
            for (int v = 0; v < 4; v++) acc[i][j][v] = 0.f;

    const int nch = K / BK;
    LOAD_CHUNK(0, sb);          CP_COMMIT();
    LOAD_CHUNK(BK, sb + STAGE); CP_COMMIT();

    for (int ch = 0; ch < nch; ch++) {
        CP_WAIT1();
        __syncthreads();
        const uint32_t base = sb + (uint32_t)(ch & 1) * STAGE;

        #pragma unroll
        for (int ks = 0; ks < 2; ks++) {
            uint32_t ah[4][4], al[4][4], bh[4][2], bl[4][2];
            #pragma unroll
            for (int mt = 0; mt < 4; mt++) {
                int row = a_row_base + mt * 16;
                int seg = a_seg_base + ks * 2;
                uint32_t off = swz(row, seg);
                ldsm4(ah[mt], base + OFF_AH + off);
                ldsm4(al[mt], base + OFF_AL + off);
            }
            #pragma unroll
            for (int nt = 0; nt < 4; nt++) {
                int row = b_row_base + nt * 8;
                int seg = b_seg_base + ks * 2;
                uint32_t off = swz(row, seg);
                ldsm2(bh[nt], base + OFF_BH + off);
                ldsm2(bl[nt], base + OFF_BL + off);
            }
            #pragma unroll
            for (int mt = 0; mt < 4; mt++)
                #pragma unroll
                for (int nt = 0; nt < 4; nt++) {
                    mma16816(acc[mt][nt], ah[mt], bh[nt]);
                    mma16816(acc[mt][nt], ah[mt], bl[nt]);
                    mma16816(acc[mt][nt], al[mt], bh[nt]);
                }
        }
        __syncthreads();
        if (ch + 2 < nch) LOAD_CHUNK((ch + 2) * BK, base);
        CP_COMMIT();
    }

    #pragma unroll
    for (int mt = 0; mt < 4; mt++) {
        int r0 = m0 + wm + mt * 16 + (lane >> 2);
        #pragma unroll
        for (int nt = 0; nt < 4; nt++) {
            int c0 = n0 + wn + nt * 8 + (lane & 3) * 2;
            float2 v0 = make_float2(acc[mt][nt][0], acc[mt][nt][1]);
            float2 v1 = make_float2(acc[mt][nt][2], acc[mt][nt][3]);
            *(float2*)(C + (size_t)r0 * N + c0)       = v0;
            *(float2*)(C + (size_t)(r0 + 8) * N + c0) = v1;
        }
    }
#undef LOAD_CHUNK
}

// ============================================================
// conversions
// ============================================================
__global__ void split2(const float* __restrict__ src, __nv_bfloat16* __restrict__ hi,
                       __nv_bfloat16* __restrict__ lo, int n2)
{
    int i = blockIdx.x * blockDim.x + threadIdx.x;
    if (i < n2) {
        float2 v = ((const float2*)src)[i];
        __nv_bfloat16 hx = __float2bfloat16(v.x), hy = __float2bfloat16(v.y);
        float rx = v.x - __bfloat162float(hx);
        float ry = v.y - __bfloat162float(hy);
        ((__nv_bfloat162*)hi)[i] = __halves2bfloat162(hx, hy);
        ((__nv_bfloat162*)lo)[i] = __halves2bfloat162(__float2bfloat16(rx), __float2bfloat16(ry));
    }
}

__global__ void transpose_split(const float* __restrict__ W, __nv_bfloat16* __restrict__ Th,
                                __nv_bfloat16* __restrict__ Tl, int K, int N)
{
    __shared__ float tile[32][33];
    int tx = threadIdx.x, ty = threadIdx.y;
    int n = blockIdx.x * 32 + tx;
    #pragma unroll
    for (int j = 0; j < 4; j++) {
        int k = blockIdx.y * 32 + ty + j * 8;
        tile[ty + j * 8][tx] = W[(size_t)k * N + n];
    }
    __syncthreads();
    int k2 = blockIdx.y * 32 + tx;
    #pragma unroll
    for (int j = 0; j < 4; j++) {
        int n2 = blockIdx.x * 32 + ty + j * 8;
        float v = tile[tx][ty + j * 8];
        __nv_bfloat16 h = __float2bfloat16(v);
        Th[(size_t)n2 * K + k2] = h;
        Tl[(size_t)n2 * K + k2] = __float2bfloat16(v - __bfloat162float(h));
    }
}

// ============================================================
// rope + layout change + hi/lo split
// q: [b,s,h,d] fp32 -> [b,h,s,d] bf16 hi/lo, rope, *1/sqrt(HD)
// k: same with NKV heads, rope, no scale. v: split only.
// ============================================================
__global__ void rope_split(const float* __restrict__ q, const float* __restrict__ k,
                           const float* __restrict__ v,
                           const float* __restrict__ cos_, const float* __restrict__ sin_,
                           __nv_bfloat16* qh, __nv_bfloat16* ql,
                           __nv_bfloat16* kh, __nv_bfloat16* kl,
                           __nv_bfloat16* vh, __nv_bfloat16* vl)
{
    const int HD2 = HD / 2;
    const int nqp = BATCH * SEQ * NH * HD2;
    const int nkp = BATCH * SEQ * NKV * HD2;
    const float qscale = 0.08838834764831845f;
    int idx = blockIdx.x * blockDim.x + threadIdx.x;
    if (idx < nqp) {
        int i = idx % HD2;
        int h = (idx / HD2) % NH;
        int s = (idx / (HD2 * NH)) % SEQ;
        int b = idx / (HD2 * NH * SEQ);
        float2 x = *(const float2*)(q + ((size_t)(b * SEQ + s) * NH + h) * HD + 2 * i);
        float c = cos_[s * HD2 + i], sn = sin_[s * HD2 + i];
        float outr = (x.x * c - x.y * sn) * qscale;
        float outi = (x.x * sn + x.y * c) * qscale;
        __nv_bfloat16 hr = __float2bfloat16(outr), hi2 = __float2bfloat16(outi);
        size_t o = ((size_t)(b * NH + h) * SEQ + s) * HD + 2 * i;
        *(__nv_bfloat162*)(qh + o) = __halves2bfloat162(hr, hi2);
        *(__nv_bfloat162*)(ql + o) = __halves2bfloat162(
            __float2bfloat16(outr - __bfloat162float(hr)),
            __float2bfloat16(outi - __bfloat162float(hi2)));
    } else if (idx < nqp + 2 * nkp) {
        int j = idx - nqp;
        int isv = j >= nkp;
        if (isv) j -= nkp;
        int i = j % HD2;
        int h = (j / HD2) % NKV;
        int s = (j / (HD2 * NKV)) % SEQ;
        int b = j / (HD2 * NKV * SEQ);
        const float* src = isv ? v : k;
        float2 x = *(const float2*)(src + ((size_t)(b * SEQ + s) * NKV + h) * HD + 2 * i);
        float outr, outi;
        if (isv) { outr = x.x; outi = x.y; }
        else {
            float c = cos_[s * HD2 + i], sn = sin_[s * HD2 + i];
            outr = x.x * c - x.y * sn;
            outi = x.x * sn + x.y * c;
        }
        __nv_bfloat16 hr = __float2bfloat16(outr), hi2 = __float2bfloat16(outi);
        size_t o = ((size_t)(b * NKV + h) * SEQ + s) * HD + 2 * i;
        __nv_bfloat16* dh = isv ? vh : kh;
        __nv_bfloat16* dl = isv ? vl : kl;
        *(__nv_bfloat162*)(dh + o) = __halves2bfloat162(hr, hi2);
        *(__nv_bfloat162*)(dl + o) = __halves2bfloat162(
            __float2bfloat16(outr - __bfloat162float(hr)),
            __float2bfloat16(outi - __bfloat162float(hi2)));
    }
}

// ============================================================
// flash attention, mma.sync split-bf16 (3-term QK, 3-term PV)
// grid (SEQ/64, NH, BATCH), 256 threads (warps: 4 row-groups x 2 halves)
// smem: 3 KV stages (kh,kl,vh,vl 16KB each) + Q(32KB, reused for P+red)
// ============================================================
#define NTILE (SEQ/64)
#define KVSTG 65536u
#define QOFF  (3u*KVSTG)              // 196608: Qh(16K) Ql(16K); later Ph(8K) Pl(8K) red(1K)
#define PH_OFF QOFF
#define PL_OFF (QOFF + 8192u)
#define RED_OFF (QOFF + 16384u)
#define ATT_SMEM (QOFF + 32768u)      // 229376

__device__ __forceinline__ uint32_t sw256(int row, int boff) {
    return (uint32_t)row * 256u + (uint32_t)(boff ^ ((row & 7) << 4));
}
__device__ __forceinline__ uint32_t sw128(int row, int boff) {
    return (uint32_t)row * 128u + (uint32_t)(boff ^ ((row & 7) << 4));
}

__global__ void __launch_bounds__(256) attn_mma(
    const __nv_bfloat16* __restrict__ qh, const __nv_bfloat16* __restrict__ ql,
    const __nv_bfloat16* __restrict__ kh, const __nv_bfloat16* __restrict__ kl,
    const __nv_bfloat16* __restrict__ vh, const __nv_bfloat16* __restrict__ vl,
    __nv_bfloat16* __restrict__ outh, __nv_bfloat16* __restrict__ outl)
{
    extern __shared__ char sm[];
    const uint32_t sb = smem_u32(sm);
    const int t = threadIdx.x, lane = t & 31, w = t >> 5;
    const int wm = w & 3, wn = w >> 2;
    const int qt = blockIdx.x, h = blockIdx.y, b = blockIdx.z;
    const int kvh = h >> 2;

    const __nv_bfloat16* qhg = qh + ((size_t)(b * NH + h) * SEQ + qt * 64) * HD;
    const __nv_bfloat16* qlg = ql + ((size_t)(b * NH + h) * SEQ + qt * 64) * HD;
    const size_t kvb = (size_t)(b * NKV + kvh) * SEQ * HD;

    // ---- Q -> smem (swizzled) ----
    {
        int r = t >> 2, seg = t & 3;
        #pragma unroll
        for (int j = 0; j < 4; j++) {
            int boff = seg * 64 + j * 16;               // bytes in row
            uint4 a = *(const uint4*)(qhg + (size_t)r * HD + boff / 2);
            *(uint4*)(sm + QOFF + sw256(r, boff)) = a;
            uint4 c = *(const uint4*)(qlg + (size_t)r * HD + boff / 2);
            *(uint4*)(sm + QOFF + 16384u + sw256(r, boff)) = c;
        }
    }

    // ---- KV tile loader ----
    const int lrow = t >> 2, lseg = t & 3;
#define LOAD_KV(kt, stg) do {                                                   \
    uint32_t bufb = sb + (uint32_t)(stg) * KVSTG;                               \
    size_t grow = kvb + ((size_t)(kt) * 64 + lrow) * HD;                        \
    _Pragma("unroll")                                                           \
    for (int j = 0; j < 4; j++) {                                               \
        int boff = lseg * 64 + j * 16;                                          \
        uint32_t sd = sw256(lrow, boff);                                        \
        cp16(bufb + sd,          kh + grow + boff / 2);                         \
        cp16(bufb + 16384u + sd, kl + grow + boff / 2);                         \
        cp16(bufb + 32768u + sd, vh + grow + boff / 2);                         \
        cp16(bufb + 49152u + sd, vl + grow + boff / 2);                         \
    }                                                                           \
} while (0)

    LOAD_KV(0, 0); CP_COMMIT();
    LOAD_KV(1, 1); CP_COMMIT();
    __syncthreads();

    // ---- preload Q fragments (A operand, rows wm*16..+16, 8 k-steps) ----
    uint32_t qfh[8][4], qfl[8][4];
    {
        int ar = wm * 16 + (lane & 7) + ((lane >> 3) & 1) * 8;
        int ab = (lane >> 4) * 16;
        #pragma unroll
        for (int ks = 0; ks < 8; ks++) {
            ldsm4(qfh[ks], sb + QOFF + sw256(ar, ks * 32 + ab));
            ldsm4(qfl[ks], sb + QOFF + 16384u + sw256(ar, ks * 32 + ab));
        }
    }

    float m[2] = {-1e30f, -1e30f}, l[2] = {0.f, 0.f};
    float oacc[8][4];
    #pragma unroll
    for (int i = 0; i < 8; i++)
        #pragma unroll
        for (int j = 0; j < 4; j++) oacc[i][j] = 0.f;

    float* redm = (float*)(sm + RED_OFF);       // [2][64]
    float* reds = redm + 128;                   // [2][64]
    const int row1 = wm * 16 + (lane >> 2);
    const int row2 = row1 + 8;

    for (int kt = 0; kt < NTILE; kt++) {
        CP_WAIT1();
        __syncthreads();                                   // BAR-0: tile kt ready
        const uint32_t kbuf = sb + (uint32_t)(kt % 3) * KVSTG;
        const uint32_t vbuf = kbuf + 32768u;

        // ---- QK^T: scores 16 rows x 32 keys (this warp's half) ----
        float sacc[4][4];
        #pragma unroll
        for (int i = 0; i < 4; i++)
            #pragma unroll
            for (int j = 0; j < 4; j++) sacc[i][j] = 0.f;
        {
            int br = wn * 32 + (lane & 7) + (lane >> 4) * 8;   // combined 2-ntile B load
            int bb0 = ((lane >> 3) & 1) * 16;
            #pragma unroll
            for (int ks = 0; ks < 8; ks++) {
                #pragma unroll
                for (int np = 0; np < 2; np++) {
                    uint32_t bh[4], bl[4];
                    uint32_t off = sw256(br + np * 16, ks * 32 + bb0);
                    ldsm4(bh, kbuf + off);
                    ldsm4(bl, kbuf + 16384u + off);
                    mma16816(sacc[np * 2],     qfh[ks], bh + 0);
                    mma16816(sacc[np * 2],     qfh[ks], bl + 0);
                    mma16816(sacc[np * 2],     qfl[ks], bh + 0);
                    mma16816(sacc[np * 2 + 1], qfh[ks], bh + 2);
                    mma16816(sacc[np * 2 + 1], qfh[ks], bl + 2);
                    mma16816(sacc[np * 2 + 1], qfl[ks], bh + 2);
                }
            }
        }

        // ---- online softmax ----
        float mx1 = -1e30f, mx2 = -1e30f;
        #pragma unroll
        for (int nt = 0; nt < 4; nt++) {
            mx1 = fmaxf(mx1, fmaxf(sacc[nt][0], sacc[nt][1]));
            mx2 = fmaxf(mx2, fmaxf(sacc[nt][2], sacc[nt][3]));
        }
        mx1 = fmaxf(mx1, __shfl_xor_sync(0xffffffffu, mx1, 1));
        mx1 = fmaxf(mx1, __shfl_xor_sync(0xffffffffu, mx1, 2));
        mx2 = fmaxf(mx2, __shfl_xor_sync(0xffffffffu, mx2, 1));
        mx2 = fmaxf(mx2, __shfl_xor_sync(0xffffffffu, mx2, 2));
        if ((lane & 3) == 0) {
            redm[wn * 64 + row1] = mx1;
            redm[wn * 64 + row2] = mx2;
        }
        __syncthreads();                                   // BAR-A
        if (kt + 2 < NTILE) LOAD_KV(kt + 2, (kt + 2) % 3);
        CP_COMMIT();

        float mn1 = fmaxf(m[0], fmaxf(redm[row1], redm[64 + row1]));
        float mn2 = fmaxf(m[1], fmaxf(redm[row2], redm[64 + row2]));
        float al1 = __expf(m[0] - mn1), al2 = __expf(m[1] - mn2);
        float p[4][4], s1 = 0.f, s2 = 0.f;
        #pragma unroll
        for (int nt = 0; nt < 4; nt++) {
            p[nt][0] = __expf(sacc[nt][0] - mn1);
            p[nt][1] = __expf(sacc[nt][1] - mn1);
            p[nt][2] = __expf(sacc[nt][2] - mn2);
            p[nt][3] = __expf(sacc[nt][3] - mn2);
            s1 += p[nt][0] + p[nt][1];
            s2 += p[nt][2] + p[nt][3];
        }
        s1 += __shfl_xor_sync(0xffffffffu, s1, 1);
        s1 += __shfl_xor_sync(0xffffffffu, s1, 2);
        s2 += __shfl_xor_sync(0xffffffffu, s2, 1);
        s2 += __shfl_xor_sync(0xffffffffu, s2, 2);
        if ((lane & 3) == 0) {
            reds[wn * 64 + row1] = s1;
            reds[wn * 64 + row2] = s2;
        }
        // store P (hi/lo) to smem
        {
            int cb = wn * 64 + (lane & 3) * 4;
            #pragma unroll
            for (int nt = 0; nt < 4; nt++) {
                float h0 = p[nt][0], h1 = p[nt][1], h2 = p[nt][2], h3 = p[nt][3];
                uint32_t ph01 = packbf(h0, h1), ph23 = packbf(h2, h3);
                __nv_bfloat162 b01 = *(__nv_bfloat162*)&ph01;
                __nv_bfloat162 b23 = *(__nv_bfloat162*)&ph23;
                uint32_t pl01 = packbf(h0 - __bfloat162float(b01.x), h1 - __bfloat162float(b01.y));
                uint32_t pl23 = packbf(h2 - __bfloat162float(b23.x), h3 - __bfloat162float(b23.y));
                uint32_t o1 = sw128(row1, cb + nt * 16);
                uint32_t o2 = sw128(row2, cb + nt * 16);
                *(uint32_t*)(sm + PH_OFF + o1) = ph01;
                *(uint32_t*)(sm + PH_OFF + o2) = ph23;
                *(uint32_t*)(sm + PL_OFF + o1) = pl01;
                *(uint32_t*)(sm + PL_OFF + o2) = pl23;
            }
        }
        __syncthreads();                                   // BAR-B (sums + P visible)
        {
            float tot1 = reds[row1] + reds[64 + row1];
            float tot2 = reds[row2] + reds[64 + row2];
            l[0] = l[0] * al1 + tot1;
            l[1] = l[1] * al2 + tot2;
            m[0] = mn1; m[1] = mn2;
            #pragma unroll
            for (int nt = 0; nt < 8; nt++) {
                oacc[nt][0] *= al1; oacc[nt][1] *= al1;
                oacc[nt][2] *= al2; oacc[nt][3] *= al2;
            }
        }

        // ---- PV: O[16 rows][64 d (this half)] += P @ V ----
        {
            int par = wm * 16 + (lane & 7) + ((lane >> 3) & 1) * 8;
            int pab = (lane >> 4) * 16;
            int vr0 = (lane & 7) + ((lane >> 3) & 1) * 8;
            int vb0 = wn * 128 + (lane >> 4) * 16;
            #pragma unroll
            for (int ks = 0; ks < 4; ks++) {
                uint32_t pfh[4], pfl[4];
                ldsm4(pfh, sb + PH_OFF + sw128(par, ks * 32 + pab));
                ldsm4(pfl, sb + PL_OFF + sw128(par, ks * 32 + pab));
                #pragma unroll
                for (int np = 0; np < 4; np++) {
                    uint32_t wh[4], wl[4];
                    uint32_t off = sw256(ks * 16 + vr0, vb0 + np * 32);
                    ldsm4t(wh, vbuf + off);
                    ldsm4t(wl, vbuf + 16384u + off);
                    mma16816(oacc[np * 2],     pfh, wh + 0);
                    mma16816(oacc[np * 2],     pfh, wl + 0);
                    mma16816(oacc[np * 2],     pfl, wh + 0);
                    mma16816(oacc[np * 2 + 1], pfh, wh + 2);
                    mma16816(oacc[np * 2 + 1], pfh, wl + 2);
                    mma16816(oacc[np * 2 + 1], pfl, wh + 2);
                }
            }
        }
        __syncthreads();                                   // BAR-C (P reads done)
    }

    // ---- epilogue: normalize, split to bf16 hi/lo, write [b,s,h*d] ----
    {
        float inv1 = 1.f / l[0], inv2 = 1.f / l[1];
        int rg1 = qt * 64 + row1, rg2 = qt * 64 + row2;
        size_t b1 = ((size_t)(b * SEQ + rg1) * NH + h) * HD;
        size_t b2 = ((size_t)(b * SEQ + rg2) * NH + h) * HD;
        #pragma unroll
        for (int nt = 0; nt < 8; nt++) {
            int c0 = wn * 64 + nt * 8 + (lane & 3) * 2;
            float f0 = oacc[nt][0] * inv1, f1 = oacc[nt][1] * inv1;
            float f2 = oacc[nt][2] * inv2, f3 = oacc[nt][3] * inv2;
            uint32_t h01 = packbf(f0, f1), h23 = packbf(f2, f3);
            __nv_bfloat162 bb01 = *(__nv_bfloat162*)&h01;
            __nv_bfloat162 bb23 = *(__nv_bfloat162*)&h23;
            uint32_t l01 = packbf(f0 - __bfloat162float(bb01.x), f1 - __bfloat162float(bb01.y));
            uint32_t l23 = packbf(f2 - __bfloat162float(bb23.x), f3 - __bfloat162float(bb23.y));
            *(uint32_t*)(outh + b1 + c0) = h01;
            *(uint32_t*)(outh + b2 + c0) = h23;
            *(uint32_t*)(outl + b1 + c0) = l01;
            *(uint32_t*)(outl + b2 + c0) = l23;
        }
    }
#undef LOAD_KV
}

// ============================================================
// launch
// ============================================================
extern "C" void kernel_launch(void* const* d_in, const int* in_sizes, int n_in,
                              void* d_out, int out_size)
{
    const float* x  = (const float*)d_in[0];
    const float* wq = (const float*)d_in[1];
    const float* wk = (const float*)d_in[2];
    const float* wv = (const float*)d_in[3];
    const float* wo = (const float*)d_in[4];
    const float* fcos = (const float*)d_in[7];
    const float* fsin = (const float*)d_in[8];
    float* out = (float*)d_out;

    float *gq, *gk, *gv;
    __nv_bfloat16 *xh, *xl, *wqTh, *wqTl, *wkTh, *wkTl, *wvTh, *wvTl, *woTh, *woTl;
    __nv_bfloat16 *aoh, *aol, *pqh, *pql, *pkh, *pkl, *pvh, *pvl;
    cudaGetSymbolAddress((void**)&gq, g_q);
    cudaGetSymbolAddress((void**)&gk, g_k);
    cudaGetSymbolAddress((void**)&gv, g_v);
    cudaGetSymbolAddress((void**)&xh, g_xh);     cudaGetSymbolAddress((void**)&xl, g_xl);
    cudaGetSymbolAddress((void**)&wqTh, g_wqTh); cudaGetSymbolAddress((void**)&wqTl, g_wqTl);
    cudaGetSymbolAddress((void**)&wkTh, g_wkTh); cudaGetSymbolAddress((void**)&wkTl, g_wkTl);
    cudaGetSymbolAddress((void**)&wvTh, g_wvTh); cudaGetSymbolAddress((void**)&wvTl, g_wvTl);
    cudaGetSymbolAddress((void**)&woTh, g_woTh); cudaGetSymbolAddress((void**)&woTl, g_woTl);
    cudaGetSymbolAddress((void**)&aoh, g_aoh);   cudaGetSymbolAddress((void**)&aol, g_aol);
    cudaGetSymbolAddress((void**)&pqh, g_qh);    cudaGetSymbolAddress((void**)&pql, g_ql);
    cudaGetSymbolAddress((void**)&pkh, g_kh);    cudaGetSymbolAddress((void**)&pkl, g_kl);
    cudaGetSymbolAddress((void**)&pvh, g_vh);    cudaGetSymbolAddress((void**)&pvl, g_vl);

    // 0) conversions
    {
        int n2 = (int)((size_t)MTOT * DIM / 2);
        split2<<<(n2 + 255) / 256, 256>>>(x, xh, xl, n2);
        transpose_split<<<dim3(NQ / 32, DIM / 32),   dim3(32, 8)>>>(wq, wqTh, wqTl, DIM, NQ);
        transpose_split<<<dim3(NKVD / 32, DIM / 32), dim3(32, 8)>>>(wk, wkTh, wkTl, DIM, NKVD);
        transpose_split<<<dim3(NKVD / 32, DIM / 32), dim3(32, 8)>>>(wv, wvTh, wvTl, DIM, NKVD);
        transpose_split<<<dim3(DIM / 32, NQ / 32),   dim3(32, 8)>>>(wo, woTh, woTl, NQ, DIM);
    }

    // 1) projections
    cudaFuncSetAttribute(gemm_mma, cudaFuncAttributeMaxDynamicSharedMemorySize, GEMM_SMEM);
    gemm_mma<<<dim3(NQ / BN,   MTOT / BM), 256, GEMM_SMEM>>>(xh, xl, wqTh, wqTl, gq, MTOT, NQ,   DIM);
    gemm_mma<<<dim3(NKVD / BN, MTOT / BM), 256, GEMM_SMEM>>>(xh, xl, wkTh, wkTl, gk, MTOT, NKVD, DIM);
    gemm_mma<<<dim3(NKVD / BN, MTOT / BM), 256, GEMM_SMEM>>>(xh, xl, wvTh, wvTl, gv, MTOT, NKVD, DIM);

    // 2) rope + split + relayout
    {
        int total = BATCH * SEQ * (NH + 2 * NKV) * (HD / 2);
        rope_split<<<(total + 255) / 256, 256>>>(gq, gk, gv, fcos, fsin,
                                                 pqh, pql, pkh, pkl, pvh, pvl);
    }

    // 3) attention (tensor cores) -> writes bf16 hi/lo directly
    {
        cudaFuncSetAttribute(attn_mma, cudaFuncAttributeMaxDynamicSharedMemorySize, ATT_SMEM);
        dim3 grid(SEQ / 64, NH, BATCH);
        attn_mma<<<grid, 256, ATT_SMEM>>>(pqh, pql, pkh, pkl, pvh, pvl, aoh, aol);
    }

    // 4) output projection
    gemm_mma<<<dim3(DIM / BN, MTOT / BM), 256, GEMM_SMEM>>>(aoh, aol, woTh, woTl, out, MTOT, DIM, NQ);
}